// round 14
// baseline (speedup 1.0000x reference)
#include <cuda_runtime.h>
#include <cuda_fp16.h>
#include <math.h>
#include <stdint.h>

// ---------------------------------------------------------------------------
// EmbedMatcher on GB300 (sm_103 plain PTX -> mma.sync fp16 tensor cores).
//  - fp16 embedding table (converted per call, merged into split_all): gather
//    traffic halves and the 51MB table is L2-resident.
//  - fp16 XW gate buffer: recurrent CELL GEMMs read half the bytes.
//  - fp16 single-segment GEMMs, fp32 accumulate; K=256 loaded fully up front
//    (one cp.async group, one sync), 96KB smem, 2 CTAs/SM.
//  - Split-K=2 on RES (folded into ln_split). NB epilogue in-GEMM.
//  - Gate-interleaved packing: LSTM cell fused into GEMM epilogue.
//  - Dead-gate elimination (N 2048->1024) + rank-1 support factorization.
// ---------------------------------------------------------------------------

__device__ __forceinline__ uint32_t smem_u32(const void* p) {
    uint32_t a;
    asm("{ .reg .u64 t; cvta.to.shared.u64 t, %1; cvt.u32.u64 %0, t; }"
        : "=r"(a) : "l"(p));
    return a;
}

// ================= fp32 scratch =================
constexpr size_t PSTRIDE_RES = 4224UL * 256;

constexpr size_t N_INVQ = 8320;
constexpr size_t N_ZP   = 2 * PSTRIDE_RES;
constexpr size_t N_QG   = 4224UL * 256;
constexpr size_t N_SN   = 256;
constexpr size_t N_GB0  = 1024;
constexpr size_t N_GB1  = 1024;
constexpr size_t N_C    = 4096UL * 256;
constexpr size_t N_H    = 4096UL * 256;

constexpr size_t O_INVQ = 0;
constexpr size_t O_ZP   = O_INVQ + N_INVQ;
constexpr size_t O_QG   = O_ZP   + N_ZP;
constexpr size_t O_SN   = O_QG   + N_QG;
constexpr size_t O_GB0  = O_SN   + N_SN;
constexpr size_t O_GB1  = O_GB0  + N_GB0;
constexpr size_t O_C    = O_GB1  + N_GB1;
constexpr size_t O_H    = O_C    + N_C;
constexpr size_t SCRATCH_TOTAL = O_H + N_H;
__device__ float g_scratch[SCRATCH_TOTAL];

// ================= fp16 scratch =================
constexpr size_t EMB_ELEMS = 200001UL * 128;   // 25,600,128 (divisible by 8)

constexpr size_t H_BUFQ = 0;
constexpr size_t H_QNB  = H_BUFQ + 8320UL * 256;
constexpr size_t H_HQ   = H_QNB  + 4224UL * 256;
constexpr size_t H_QG   = H_HQ   + 4224UL * 512;
constexpr size_t H_HH   = H_QG   + 4224UL * 256;
constexpr size_t H_GW   = H_HH   + 4096UL * 256;
constexpr size_t H_P1   = H_GW   + 128UL * 256;
constexpr size_t H_P2   = H_P1   + 512UL * 256;
constexpr size_t H_WIH  = H_P2   + 256UL * 512;
constexpr size_t H_WHH  = H_WIH  + 1024UL * 256;
constexpr size_t H_XW   = H_WHH  + 1024UL * 256;
constexpr size_t H_EMB  = H_XW   + 4096UL * 1024;
constexpr size_t HF_TOTAL = H_EMB + EMB_ELEMS;
__device__ __align__(128) __half g_hf[HF_TOTAL];

// ================= helpers =================
__device__ __forceinline__ float sigf(float x) { return 1.0f / (1.0f + expf(-x)); }

__device__ __forceinline__ float block_sum256(float v, float* sbuf) {
    int t = threadIdx.x;
    sbuf[t] = v;
    __syncthreads();
    #pragma unroll
    for (int s = 128; s > 0; s >>= 1) {
        if (t < s) sbuf[t] += sbuf[t + s];
        __syncthreads();
    }
    float r = sbuf[0];
    __syncthreads();
    return r;
}

// ================= fused gather over fp16 table ==============================
// Block = one (row, side). 128 threads: pair = t>>4 handles neighbor n = j*8+pair,
// half-lane = t&15 covers 8 columns (uint4 = 8 halfs). Cross-pair smem reduce.
__global__ void gather_all_kernel(const int* __restrict__ qlc, const int* __restrict__ qld,
                                  const int* __restrict__ qrc, const int* __restrict__ qrd,
                                  const int* __restrict__ slc, const int* __restrict__ sld,
                                  const int* __restrict__ src_, const int* __restrict__ srd,
                                  const __half* __restrict__ embh,
                                  __half* __restrict__ bq,
                                  float* __restrict__ invq)
{
    __shared__ int sc[128];
    __shared__ float redr[8][16][8];
    __shared__ float rede[8][16][8];
    int b = blockIdx.x;
    const int* conn; const int* deg; int r, row;
    if (b < 4096)      { r = b;        conn = qlc;  deg = qld; row = 2 * r; }
    else if (b < 8192) { r = b - 4096; conn = qrc;  deg = qrd; row = 2 * r + 1; }
    else if (b < 8197) { r = b - 8192; conn = slc;  deg = sld; row = 8192 + 2 * r; }
    else               { r = b - 8197; conn = src_; deg = srd; row = 8192 + 2 * r + 1; }
    int t = threadIdx.x;   // 128
    int hl = t & 15;       // column group (8 halfs)
    int pr = t >> 4;       // 0..7
    sc[t] = conn[r * 128 + t];
    __syncthreads();

    float sr[8], se[8];
    #pragma unroll
    for (int q = 0; q < 8; q++) { sr[q] = 0.f; se[q] = 0.f; }
    #pragma unroll
    for (int j = 0; j < 8; j++) {
        int n = j * 8 + pr;   // neighbor 0..63
        uint4 vr = __ldg((const uint4*)(embh + (size_t)sc[2 * n]     * 128) + hl);
        uint4 ve = __ldg((const uint4*)(embh + (size_t)sc[2 * n + 1] * 128) + hl);
        const uint32_t* pr32 = (const uint32_t*)&vr;
        const uint32_t* pe32 = (const uint32_t*)&ve;
        #pragma unroll
        for (int q = 0; q < 4; q++) {
            float2 fr = __half22float2(*(const __half2*)&pr32[q]);
            float2 fe = __half22float2(*(const __half2*)&pe32[q]);
            sr[2 * q]     += fr.x; sr[2 * q + 1] += fr.y;
            se[2 * q]     += fe.x; se[2 * q + 1] += fe.y;
        }
    }
    #pragma unroll
    for (int q = 0; q < 8; q++) { redr[pr][hl][q] = sr[q]; rede[pr][hl][q] = se[q]; }
    __syncthreads();

    // thread t -> column t (= (t>>3)*8 + (t&7)); sum 8 partials
    float accr = 0.f, acce = 0.f;
    int chl = t >> 3, cq = t & 7;
    #pragma unroll
    for (int p = 0; p < 8; p++) {
        accr += redr[p][chl][cq];
        acce += rede[p][chl][cq];
    }
    bq[(size_t)row * 256 + t]       = __float2half(accr);
    bq[(size_t)row * 256 + 128 + t] = __float2half(acce);
    if (t == 0) invq[row] = 1.0f / (float)max(deg[r], 1);
}

// ================= merged weight conversion + gb0 + emb->fp16 ================
// blocks: [0,128) gcn | [128,640) p1 | [640,1152) p2 | [1152,2176) w_ih packed
//         [2176,3200) w_hh packed | 3200 gb0 | [3201, 3201+12501) emb fp16
__global__ void split_all_kernel(const float* __restrict__ gcn_w,
                                 const float* __restrict__ p1w,
                                 const float* __restrict__ p2w,
                                 const float* __restrict__ w_ih,
                                 const float* __restrict__ w_hh,
                                 const float* __restrict__ b_ih,
                                 const float* __restrict__ b_hh,
                                 const float* __restrict__ emb,
                                 __half* __restrict__ gw,
                                 __half* __restrict__ p1,
                                 __half* __restrict__ p2,
                                 __half* __restrict__ wih,
                                 __half* __restrict__ whh,
                                 __half* __restrict__ embh,
                                 float* __restrict__ gb0)
{
    int b = blockIdx.x, t = threadIdx.x;
    if (b >= 3201) {  // emb conversion: 8 floats per thread
        size_t i8 = (size_t)(b - 3201) * 256 + t;
        if (i8 < EMB_ELEMS / 8) {
            size_t base = i8 * 8;
            float4 f0 = *(const float4*)(emb + base);
            float4 f1 = *(const float4*)(emb + base + 4);
            uint4 o;
            __half2 h;
            h = __floats2half2_rn(f0.x, f0.y); o.x = *(uint32_t*)&h;
            h = __floats2half2_rn(f0.z, f0.w); o.y = *(uint32_t*)&h;
            h = __floats2half2_rn(f1.x, f1.y); o.z = *(uint32_t*)&h;
            h = __floats2half2_rn(f1.z, f1.w); o.w = *(uint32_t*)&h;
            *(uint4*)(embh + base) = o;
        }
        return;
    }
    if (b == 3200) {
        #pragma unroll
        for (int k = 0; k < 4; k++) {
            int col = k * 256 + t;
            int g = col & 3, u = col >> 2;
            gb0[col] = b_ih[g * 512 + u] + b_hh[g * 512 + u];
        }
        return;
    }
    float v;
    __half* dst;
    int idx;
    if (b < 128)       { idx = b * 256 + t;          v = gcn_w[idx]; dst = gw; }
    else if (b < 640)  { idx = (b - 128) * 256 + t;  v = p1w[idx];   dst = p1; }
    else if (b < 1152) { idx = (b - 640) * 256 + t;  v = p2w[idx];   dst = p2; }
    else {
        const float* W; int ldw;
        if (b < 2176) { idx = (b - 1152) * 256 + t; W = w_ih; ldw = 256; dst = wih; }
        else          { idx = (b - 2176) * 256 + t; W = w_hh; ldw = 512; dst = whh; }
        int orow = idx >> 8, c = idx & 255;
        int u = orow >> 2, g = orow & 3;           // packed col = u*4+g
        v = W[(size_t)(g * 512 + u) * ldw + c];
    }
    dst[idx] = __float2half(v);
}

// ================= gb1 = gb0 + rvec; block 0 also emits SN ===================
__global__ void gb1_sn_kernel(const float* __restrict__ w_hh,
                              const float* __restrict__ QG,
                              const float* __restrict__ gb0,
                              float* __restrict__ gb1,
                              float* __restrict__ SN)
{
    __shared__ float sg[256];
    __shared__ float sbuf[256];
    int t = threadIdx.x;
    float s = 0.f;
    #pragma unroll
    for (int r = 0; r < 5; r++) s += QG[(size_t)(4096 + r) * 256 + t];
    float v = s * 0.2f;
    sg[t] = v;
    __syncthreads();
    int col = blockIdx.x * 256 + t;    // 0..1023
    int g = col & 3, u = col >> 2;
    const float* w = w_hh + (size_t)(g * 512 + u) * 512 + 256;
    float acc = 0.0f;
    #pragma unroll 8
    for (int k = 0; k < 256; k++) acc += w[k] * sg[k];
    gb1[col] = gb0[col] + acc;
    if (blockIdx.x == 0) {
        float n2 = block_sum256(v * v, sbuf);
        SN[t] = v / fmaxf(sqrtf(n2), 1e-12f);
    }
}

// ================= unified mma.sync fp16 GEMM ================================
enum { EPI_RAW0 = 0, EPI_RELU = 1, EPI_NB = 3, EPI_CELL0 = 4, EPI_CELL = 5 };

__device__ __forceinline__ void cp16(uint32_t daddr, const void* g) {
    asm volatile("cp.async.cg.shared.global [%0], [%1], 16;" :: "r"(daddr), "l"(g));
}

__device__ __forceinline__ void stage_load(char* sa, char* sb,
                                           const __half* __restrict__ Asrc,
                                           const __half* __restrict__ Bsrc,
                                           int lda, int ldb, int bm, int bn,
                                           int koff, int tid)
{
    #pragma unroll
    for (int i = 0; i < 2; i++) {
        int idx = i * 256 + tid;
        int row = idx >> 3, ch = idx & 7;
        uint32_t off = (uint32_t)(row * 128 + ch * 16);
        uint32_t sw  = off ^ ((off >> 3) & 0x70);
        cp16(smem_u32(sa + sw), Asrc + (size_t)(bm + row) * lda + koff + ch * 8);
    }
    #pragma unroll
    for (int i = 0; i < 4; i++) {
        int idx = i * 256 + tid;
        int row = idx >> 3, ch = idx & 7;
        uint32_t off = (uint32_t)(row * 128 + ch * 16);
        uint32_t sw  = off ^ ((off >> 3) & 0x70);
        cp16(smem_u32(sb + sw), Bsrc + (size_t)(bn + row) * ldb + koff + ch * 8);
    }
}

template <int EPI>
__device__ __forceinline__ void cell_store(int r, int u,
                                           float gi, float gf, float gg, float go,
                                           float* __restrict__ cvec,
                                           const float* __restrict__ qg,
                                           float* __restrict__ hout,
                                           __half* __restrict__ outh)
{
    size_t idx = (size_t)r * 256 + u;
    float cp = (EPI == EPI_CELL) ? cvec[idx] : 0.0f;
    float cn = sigf(gf) * cp + sigf(gi) * tanhf(gg);
    cvec[idx] = cn;
    float hv = qg[idx] + sigf(go) * tanhf(cn);
    hout[idx] = hv;
    outh[idx] = __float2half(hv);
}

template <int EPI>
__device__ __forceinline__ void epi_store(int gm, int gn, float v,
                                          float* __restrict__ C, int ldc,
                                          const float* __restrict__ bias,
                                          const float* __restrict__ extra,
                                          __half* __restrict__ outh)
{
    if (EPI == EPI_RAW0) {
        C[(size_t)gm * ldc + gn] = v;
    } else if (EPI == EPI_RELU) {
        float o = fmaxf(v + bias[gn], 0.0f);
        outh[(size_t)gm * ldc + gn] = __float2half(o);
    } else {  // EPI_NB
        float o = tanhf((v + 64.0f * bias[gn]) * extra[gm]);
        size_t idx = (size_t)(gm >> 1) * 256 + (size_t)(gm & 1) * 128 + gn;
        outh[idx] = __float2half(o);
    }
}

template <int EPI>
__global__ __launch_bounds__(256, 2)
void mma_gemm(const __half* __restrict__ A, int lda,
              const __half* __restrict__ B, int ldb,
              int K, size_t pstride,
              float* __restrict__ C, int ldc,
              const float* __restrict__ bias, const float* __restrict__ extra,
              __half* __restrict__ outh, __half* __restrict__ xwh,
              float* __restrict__ cvec, float* __restrict__ hout)
{
    constexpr int MI = 2;
    constexpr int ASZ = 64 * 128;          // 8 KB
    constexpr int STAGE = ASZ + 16384;     // 24 KB
    extern __shared__ char smem[];         // up to 4 stages = 96 KB
    const int tid  = threadIdx.x;
    const int wid  = tid >> 5;
    const int lane = tid & 31;
    const int bm = blockIdx.y * 64;
    const int bn = blockIdx.x * 128;
    const int zoff = blockIdx.z * K;
    if (EPI == EPI_RAW0) C += (size_t)blockIdx.z * pstride;
    const int warp_m = wid & 1;
    const int warp_n = wid >> 1;

    float acc[MI][4][4];
    #pragma unroll
    for (int mi = 0; mi < MI; mi++)
        #pragma unroll
        for (int nj = 0; nj < 4; nj++)
            #pragma unroll
            for (int q = 0; q < 4; q++) acc[mi][nj][q] = 0.0f;

    const int a_row_off = (lane & 7) + ((lane >> 3) & 1) * 8;
    const int a_ch_off  = lane >> 4;
    const int b_row_off = (lane >> 4) * 8 + (lane & 7);
    const int b_ch_off  = (lane >> 3) & 1;

    const int nt = K >> 6;   // <= 4

    for (int c = 0; c < nt; c++) {
        char* base = smem + c * STAGE;
        stage_load(base, base + ASZ, A, B, lda, ldb, bm, bn, zoff + c * 64, tid);
    }
    asm volatile("cp.async.commit_group;");
    asm volatile("cp.async.wait_group 0;");
    __syncthreads();

    for (int c = 0; c < nt; c++) {
        const uint32_t sa_base = smem_u32(smem + c * STAGE);
        const uint32_t sb_base = sa_base + ASZ;

        #pragma unroll
        for (int ks = 0; ks < 4; ks++) {
            uint32_t a[MI][4];
            #pragma unroll
            for (int mi = 0; mi < MI; mi++) {
                uint32_t row = warp_m * 32 + mi * 16 + a_row_off;
                uint32_t ch  = ks * 2 + a_ch_off;
                uint32_t off = row * 128 + ch * 16;
                uint32_t addr = sa_base + (off ^ ((off >> 3) & 0x70));
                asm volatile("ldmatrix.sync.aligned.m8n8.x4.shared.b16 {%0,%1,%2,%3}, [%4];"
                             : "=r"(a[mi][0]), "=r"(a[mi][1]), "=r"(a[mi][2]), "=r"(a[mi][3])
                             : "r"(addr));
            }
            uint32_t b[4][2];
            #pragma unroll
            for (int njp = 0; njp < 2; njp++) {
                uint32_t row = warp_n * 32 + njp * 16 + b_row_off;
                uint32_t ch  = ks * 2 + b_ch_off;
                uint32_t off = row * 128 + ch * 16;
                uint32_t addr = sb_base + (off ^ ((off >> 3) & 0x70));
                asm volatile("ldmatrix.sync.aligned.m8n8.x4.shared.b16 {%0,%1,%2,%3}, [%4];"
                             : "=r"(b[njp * 2][0]), "=r"(b[njp * 2][1]),
                               "=r"(b[njp * 2 + 1][0]), "=r"(b[njp * 2 + 1][1])
                             : "r"(addr));
            }
            #pragma unroll
            for (int mi = 0; mi < MI; mi++)
                #pragma unroll
                for (int nj = 0; nj < 4; nj++)
                    asm volatile(
                        "mma.sync.aligned.m16n8k16.row.col.f32.f16.f16.f32 "
                        "{%0,%1,%2,%3}, {%4,%5,%6,%7}, {%8,%9}, {%0,%1,%2,%3};"
                        : "+f"(acc[mi][nj][0]), "+f"(acc[mi][nj][1]),
                          "+f"(acc[mi][nj][2]), "+f"(acc[mi][nj][3])
                        : "r"(a[mi][0]), "r"(a[mi][1]), "r"(a[mi][2]), "r"(a[mi][3]),
                          "r"(b[nj][0]), "r"(b[nj][1]));
        }
    }

    if (EPI == EPI_CELL0 || EPI == EPI_CELL) {
        #pragma unroll
        for (int mi = 0; mi < MI; mi++) {
            int m0 = bm + warp_m * 32 + mi * 16 + (lane >> 2);
            #pragma unroll
            for (int nj = 0; nj < 4; nj++) {
                int n0 = bn + warp_n * 32 + nj * 8 + (lane & 3) * 2;
                float v0 = acc[mi][nj][0], v1 = acc[mi][nj][1];
                float v2 = acc[mi][nj][2], v3 = acc[mi][nj][3];
                if (EPI == EPI_CELL0) {
                    *(__half2*)(xwh + (size_t)m0 * 1024 + n0) =
                        __floats2half2_rn(v0, v1);
                    *(__half2*)(xwh + (size_t)(m0 + 8) * 1024 + n0) =
                        __floats2half2_rn(v2, v3);
                } else {
                    float2 x0 = __half22float2(*(const __half2*)(xwh + (size_t)m0 * 1024 + n0));
                    float2 x1 = __half22float2(*(const __half2*)(xwh + (size_t)(m0 + 8) * 1024 + n0));
                    v0 += x0.x; v1 += x0.y; v2 += x1.x; v3 += x1.y;
                }
                float bb0 = bias[n0], bb1 = bias[n0 + 1];
                v0 += bb0; v1 += bb1; v2 += bb0; v3 += bb1;
                float e0 = __shfl_xor_sync(0xFFFFFFFFu, v0, 1);
                float e1 = __shfl_xor_sync(0xFFFFFFFFu, v1, 1);
                float e2 = __shfl_xor_sync(0xFFFFFFFFu, v2, 1);
                float e3 = __shfl_xor_sync(0xFFFFFFFFu, v3, 1);
                if ((lane & 1) == 0) {
                    int u = n0 >> 2;
                    cell_store<EPI>(m0,     u, v0, v1, e0, e1, cvec, extra, hout, outh);
                    cell_store<EPI>(m0 + 8, u, v2, v3, e2, e3, cvec, extra, hout, outh);
                }
            }
        }
    } else {
        #pragma unroll
        for (int mi = 0; mi < MI; mi++) {
            int m0 = bm + warp_m * 32 + mi * 16 + (lane >> 2);
            #pragma unroll
            for (int nj = 0; nj < 4; nj++) {
                int n0 = bn + warp_n * 32 + nj * 8 + (lane & 3) * 2;
                epi_store<EPI>(m0,     n0,     acc[mi][nj][0], C, ldc, bias, extra, outh);
                epi_store<EPI>(m0,     n0 + 1, acc[mi][nj][1], C, ldc, bias, extra, outh);
                epi_store<EPI>(m0 + 8, n0,     acc[mi][nj][2], C, ldc, bias, extra, outh);
                epi_store<EPI>(m0 + 8, n0 + 1, acc[mi][nj][3], C, ldc, bias, extra, outh);
            }
        }
    }
}

// ================= layernorm over RES partials + fp16 out ====================
__global__ void ln_split_kernel(const float* __restrict__ ZP,
                                const __half* __restrict__ QNB,
                                const float* __restrict__ p2b,
                                const float* __restrict__ g,
                                const float* __restrict__ bb,
                                float* __restrict__ out,
                                __half* __restrict__ oh)
{
    __shared__ float sbuf[256];
    int r = blockIdx.x, t = threadIdx.x;
    size_t idx = (size_t)r * 256 + t;
    float z = ZP[idx] + ZP[PSTRIDE_RES + idx] + p2b[t] + __half2float(QNB[idx]);
    float mu = block_sum256(z, sbuf) * (1.0f / 256.0f);
    float d = z - mu;
    float var = block_sum256(d * d, sbuf) * (1.0f / 255.0f);
    float o = g[t] * d / (sqrtf(var) + 1e-6f) + bb[t];
    out[idx] = o;
    oh[idx] = __float2half(o);
}

// ================= final cosine similarity =================
__global__ void final_kernel(const float* __restrict__ h,
                             const float* __restrict__ sn,
                             float* __restrict__ out)
{
    __shared__ float sbuf[256];
    int b = blockIdx.x, t = threadIdx.x;
    float v = h[(size_t)b * 256 + t];
    float dot = block_sum256(v * sn[t], sbuf);
    float n2  = block_sum256(v * v, sbuf);
    if (t == 0) out[b] = dot / fmaxf(sqrtf(n2), 1e-12f);
}

// ================= launch =================
extern "C" void kernel_launch(void* const* d_in, const int* in_sizes, int n_in,
                              void* d_out, int out_size)
{
    (void)in_sizes; (void)n_in; (void)out_size;
    const int*   q_l_conn = (const int*)  d_in[2];
    const int*   q_l_deg  = (const int*)  d_in[3];
    const int*   q_r_conn = (const int*)  d_in[4];
    const int*   q_r_deg  = (const int*)  d_in[5];
    const int*   s_l_conn = (const int*)  d_in[6];
    const int*   s_l_deg  = (const int*)  d_in[7];
    const int*   s_r_conn = (const int*)  d_in[8];
    const int*   s_r_deg  = (const int*)  d_in[9];
    const float* emb      = (const float*)d_in[10];
    const float* gcn_w    = (const float*)d_in[11];
    const float* gcn_bias = (const float*)d_in[12];
    const float* proj1_w  = (const float*)d_in[13];
    const float* proj1_b  = (const float*)d_in[14];
    const float* proj2_w  = (const float*)d_in[15];
    const float* proj2_b  = (const float*)d_in[16];
    const float* ln_g     = (const float*)d_in[17];
    const float* ln_b     = (const float*)d_in[18];
    const float* w_ih     = (const float*)d_in[19];
    const float* w_hh     = (const float*)d_in[20];
    const float* b_ih     = (const float*)d_in[21];
    const float* b_hh     = (const float*)d_in[22];
    float* out = (float*)d_out;

    float* S = nullptr;
    cudaGetSymbolAddress((void**)&S, g_scratch);
    __half* HF = nullptr;
    cudaGetSymbolAddress((void**)&HF, g_hf);

    float* INVQ = S + O_INVQ;  float* ZP  = S + O_ZP;    float* QG = S + O_QG;
    float* SN   = S + O_SN;
    float* GB0  = S + O_GB0;   float* GB1 = S + O_GB1;
    float* C    = S + O_C;     float* H   = S + O_H;

    __half* BQ  = HF + H_BUFQ;  __half* QNB = HF + H_QNB;
    __half* HQ  = HF + H_HQ;    __half* QGH = HF + H_QG;
    __half* HH  = HF + H_HH;    __half* GW  = HF + H_GW;
    __half* P1  = HF + H_P1;    __half* P2  = HF + H_P2;
    __half* WIH = HF + H_WIH;   __half* WHH = HF + H_WHH;
    __half* XWH = HF + H_XW;    __half* EMBH = HF + H_EMB;

    const int SM4 = 4 * (64 * 128 + 16384);  // 98304
    cudaFuncSetAttribute(mma_gemm<EPI_RAW0>,  cudaFuncAttributeMaxDynamicSharedMemorySize, SM4);
    cudaFuncSetAttribute(mma_gemm<EPI_RELU>,  cudaFuncAttributeMaxDynamicSharedMemorySize, SM4);
    cudaFuncSetAttribute(mma_gemm<EPI_NB>,    cudaFuncAttributeMaxDynamicSharedMemorySize, SM4);
    cudaFuncSetAttribute(mma_gemm<EPI_CELL0>, cudaFuncAttributeMaxDynamicSharedMemorySize, SM4);
    cudaFuncSetAttribute(mma_gemm<EPI_CELL>,  cudaFuncAttributeMaxDynamicSharedMemorySize, SM4);

    // 1) weight fp16 conversion + gb0 + emb->fp16 (one launch), then gathers
    split_all_kernel<<<3201 + 12501, 256>>>(gcn_w, proj1_w, proj2_w, w_ih, w_hh,
                                            b_ih, b_hh, emb,
                                            GW, P1, P2, WIH, WHH, EMBH, GB0);
    gather_all_kernel<<<8202, 128>>>(q_l_conn, q_l_deg, q_r_conn, q_r_deg,
                                     s_l_conn, s_l_deg, s_r_conn, s_r_deg,
                                     EMBH, BQ, INVQ);

    // 2) GCN (129 tiles of 64 rows): tanh+remap epilogue -> QNB fp16
    mma_gemm<EPI_NB><<<dim3(1, 129), 256, SM4>>>(
        BQ, 256, GW, 256, 256, 0, nullptr, 256,
        gcn_bias, INVQ, QNB, nullptr, nullptr, nullptr);

    // 3) proj1 (264 CTAs), proj2 split-K=2 (264 CTAs), LN folds partials+residual
    mma_gemm<EPI_RELU><<<dim3(4, 66), 256, SM4>>>(
        QNB, 256, P1, 256, 256, 0, nullptr, 512,
        proj1_b, nullptr, HQ, nullptr, nullptr, nullptr);
    mma_gemm<EPI_RAW0><<<dim3(2, 66, 2), 256, SM4>>>(
        HQ, 512, P2, 512, 256, PSTRIDE_RES, ZP, 256,
        nullptr, nullptr, nullptr, nullptr, nullptr, nullptr);
    ln_split_kernel<<<4101, 256>>>(ZP, QNB, proj2_b, ln_g, ln_b, QG, QGH);

    // 4) gb1 (+SN from block 0)
    gb1_sn_kernel<<<4, 256>>>(w_hh, QG, GB0, GB1, SN);

    // 5) LSTM: GEMM + fused cell epilogues (512 CTAs each); XW gates in fp16
    mma_gemm<EPI_CELL0><<<dim3(8, 64), 256, SM4>>>(
        QGH, 256, WIH, 256, 256, 0, nullptr, 1024,
        GB0, QG, HH, XWH, C, H);
    for (int t = 1; t < 4; t++) {
        mma_gemm<EPI_CELL><<<dim3(8, 64), 256, SM4>>>(
            HH, 256, WHH, 256, 256, 0, nullptr, 1024,
            GB1, QG, HH, XWH, C, H);
    }

    // 6) cosine similarity
    final_kernel<<<4096, 256>>>(H, SN, out);
}

// round 15
// speedup vs baseline: 1.0282x; 1.0282x over previous
#include <cuda_runtime.h>
#include <cuda_fp16.h>
#include <math.h>
#include <stdint.h>

// ---------------------------------------------------------------------------
// EmbedMatcher on GB300 (sm_103 plain PTX -> mma.sync fp16 tensor cores).
//  - fp32 embedding gather (L2-BW bound; per-call fp16 conversion proved a wash)
//    MERGED into the weight-split kernel: one launch covers both.
//  - fp16 XW gate buffer: recurrent CELL GEMMs read half the bytes.
//  - fp16 single-segment GEMMs, fp32 accumulate; K=256 loaded fully up front
//    (one cp.async group, one sync), 96KB smem, 2 CTAs/SM.
//  - Split-K=2 on RES (folded into ln_split). NB epilogue in-GEMM.
//  - Gate-interleaved packing: LSTM cell fused into GEMM epilogue.
//  - Dead-gate elimination (N 2048->1024) + rank-1 support factorization.
// ---------------------------------------------------------------------------

__device__ __forceinline__ uint32_t smem_u32(const void* p) {
    uint32_t a;
    asm("{ .reg .u64 t; cvta.to.shared.u64 t, %1; cvt.u32.u64 %0, t; }"
        : "=r"(a) : "l"(p));
    return a;
}

// ================= fp32 scratch =================
constexpr size_t PSTRIDE_RES = 4224UL * 256;

constexpr size_t N_INVQ = 8320;
constexpr size_t N_ZP   = 2 * PSTRIDE_RES;
constexpr size_t N_QG   = 4224UL * 256;
constexpr size_t N_SN   = 256;
constexpr size_t N_GB0  = 1024;
constexpr size_t N_GB1  = 1024;
constexpr size_t N_C    = 4096UL * 256;
constexpr size_t N_H    = 4096UL * 256;

constexpr size_t O_INVQ = 0;
constexpr size_t O_ZP   = O_INVQ + N_INVQ;
constexpr size_t O_QG   = O_ZP   + N_ZP;
constexpr size_t O_SN   = O_QG   + N_QG;
constexpr size_t O_GB0  = O_SN   + N_SN;
constexpr size_t O_GB1  = O_GB0  + N_GB0;
constexpr size_t O_C    = O_GB1  + N_GB1;
constexpr size_t O_H    = O_C    + N_C;
constexpr size_t SCRATCH_TOTAL = O_H + N_H;
__device__ float g_scratch[SCRATCH_TOTAL];

// ================= fp16 scratch =================
constexpr size_t H_BUFQ = 0;
constexpr size_t H_QNB  = H_BUFQ + 8320UL * 256;
constexpr size_t H_HQ   = H_QNB  + 4224UL * 256;
constexpr size_t H_QG   = H_HQ   + 4224UL * 512;
constexpr size_t H_HH   = H_QG   + 4224UL * 256;
constexpr size_t H_GW   = H_HH   + 4096UL * 256;
constexpr size_t H_P1   = H_GW   + 128UL * 256;
constexpr size_t H_P2   = H_P1   + 512UL * 256;
constexpr size_t H_WIH  = H_P2   + 256UL * 512;
constexpr size_t H_WHH  = H_WIH  + 1024UL * 256;
constexpr size_t H_XW   = H_WHH  + 1024UL * 256;
constexpr size_t HF_TOTAL = H_XW + 4096UL * 1024;
__device__ __align__(128) __half g_hf[HF_TOTAL];

// ================= helpers =================
__device__ __forceinline__ float sigf(float x) { return 1.0f / (1.0f + expf(-x)); }

__device__ __forceinline__ float block_sum256(float v, float* sbuf) {
    int t = threadIdx.x;
    sbuf[t] = v;
    __syncthreads();
    #pragma unroll
    for (int s = 128; s > 0; s >>= 1) {
        if (t < s) sbuf[t] += sbuf[t + s];
        __syncthreads();
    }
    float r = sbuf[0];
    __syncthreads();
    return r;
}

// ================= merged prep: weight fp16 + gb0 + ALL gathers ==============
// blocks: [0,128) gcn | [128,640) p1 | [640,1152) p2 | [1152,2176) w_ih packed
//         [2176,3200) w_hh packed | 3200 gb0 |
//         [3201, 3201+4101): gather, 2 units/block (units 0..8201).
__global__ void prep_all_kernel(const float* __restrict__ gcn_w,
                                const float* __restrict__ p1w,
                                const float* __restrict__ p2w,
                                const float* __restrict__ w_ih,
                                const float* __restrict__ w_hh,
                                const float* __restrict__ b_ih,
                                const float* __restrict__ b_hh,
                                const int* __restrict__ qlc, const int* __restrict__ qld,
                                const int* __restrict__ qrc, const int* __restrict__ qrd,
                                const int* __restrict__ slc, const int* __restrict__ sld,
                                const int* __restrict__ src_, const int* __restrict__ srd,
                                const float* __restrict__ emb,
                                __half* __restrict__ gw,
                                __half* __restrict__ p1,
                                __half* __restrict__ p2,
                                __half* __restrict__ wih,
                                __half* __restrict__ whh,
                                float* __restrict__ gb0,
                                __half* __restrict__ bq,
                                float* __restrict__ invq)
{
    int b = blockIdx.x, tid = threadIdx.x;

    if (b >= 3201) {
        // ---- gather: 2 units per block, 128 threads per unit ----
        __shared__ int sc[2][128];
        __shared__ float4 red[2][2][4][32];
        int half = tid >> 7;          // 0 or 1
        int t = tid & 127;
        int u = (b - 3201) * 2 + half;  // unit 0..8201
        const int* conn; const int* deg; int r, row;
        if (u < 4096)      { r = u;        conn = qlc;  deg = qld; row = 2 * r; }
        else if (u < 8192) { r = u - 4096; conn = qrc;  deg = qrd; row = 2 * r + 1; }
        else if (u < 8197) { r = u - 8192; conn = slc;  deg = sld; row = 8192 + 2 * r; }
        else               { r = u - 8197; conn = src_; deg = srd; row = 8192 + 2 * r + 1; }
        int w = t >> 5, l = t & 31;
        sc[half][t] = conn[r * 128 + t];
        __syncthreads();
        float4 a0 = make_float4(0.f, 0.f, 0.f, 0.f);
        float4 a1 = make_float4(0.f, 0.f, 0.f, 0.f);
        #pragma unroll 4
        for (int i = 0; i < 16; i++) {
            int n = w * 16 + i;
            float4 v0 = __ldg((const float4*)(emb + (size_t)sc[half][2 * n]     * 128) + l);
            float4 v1 = __ldg((const float4*)(emb + (size_t)sc[half][2 * n + 1] * 128) + l);
            a0.x += v0.x; a0.y += v0.y; a0.z += v0.z; a0.w += v0.w;
            a1.x += v1.x; a1.y += v1.y; a1.z += v1.z; a1.w += v1.w;
        }
        red[half][0][w][l] = a0;
        red[half][1][w][l] = a1;
        __syncthreads();
        if (t < 64) {
            int which = t >> 5, ll = t & 31;
            float4 p0 = red[half][which][0][ll], q1 = red[half][which][1][ll];
            float4 q2 = red[half][which][2][ll], q3 = red[half][which][3][ll];
            float s[4];
            s[0] = p0.x + q1.x + q2.x + q3.x;
            s[1] = p0.y + q1.y + q2.y + q3.y;
            s[2] = p0.z + q1.z + q2.z + q3.z;
            s[3] = p0.w + q1.w + q2.w + q3.w;
            size_t base = (size_t)row * 256 + which * 128 + ll * 4;
            #pragma unroll
            for (int j = 0; j < 4; j++) bq[base + j] = __float2half(s[j]);
        }
        if (t == 0) invq[row] = 1.0f / (float)max(deg[r], 1);
        return;
    }

    if (b == 3200) {
        #pragma unroll
        for (int k = 0; k < 4; k++) {
            int col = k * 256 + tid;
            int g = col & 3, u2 = col >> 2;
            gb0[col] = b_ih[g * 512 + u2] + b_hh[g * 512 + u2];
        }
        return;
    }
    float v;
    __half* dst;
    int idx;
    if (b < 128)       { idx = b * 256 + tid;          v = gcn_w[idx]; dst = gw; }
    else if (b < 640)  { idx = (b - 128) * 256 + tid;  v = p1w[idx];   dst = p1; }
    else if (b < 1152) { idx = (b - 640) * 256 + tid;  v = p2w[idx];   dst = p2; }
    else {
        const float* W; int ldw;
        if (b < 2176) { idx = (b - 1152) * 256 + tid; W = w_ih; ldw = 256; dst = wih; }
        else          { idx = (b - 2176) * 256 + tid; W = w_hh; ldw = 512; dst = whh; }
        int orow = idx >> 8, c = idx & 255;
        int u2 = orow >> 2, g = orow & 3;          // packed col = u*4+g
        v = W[(size_t)(g * 512 + u2) * ldw + c];
    }
    dst[idx] = __float2half(v);
}

// ================= gb1 = gb0 + rvec; block 0 also emits SN ===================
__global__ void gb1_sn_kernel(const float* __restrict__ w_hh,
                              const float* __restrict__ QG,
                              const float* __restrict__ gb0,
                              float* __restrict__ gb1,
                              float* __restrict__ SN)
{
    __shared__ float sg[256];
    __shared__ float sbuf[256];
    int t = threadIdx.x;
    float s = 0.f;
    #pragma unroll
    for (int r = 0; r < 5; r++) s += QG[(size_t)(4096 + r) * 256 + t];
    float v = s * 0.2f;
    sg[t] = v;
    __syncthreads();
    int col = blockIdx.x * 256 + t;    // 0..1023
    int g = col & 3, u = col >> 2;
    const float* w = w_hh + (size_t)(g * 512 + u) * 512 + 256;
    float acc = 0.0f;
    #pragma unroll 8
    for (int k = 0; k < 256; k++) acc += w[k] * sg[k];
    gb1[col] = gb0[col] + acc;
    if (blockIdx.x == 0) {
        float n2 = block_sum256(v * v, sbuf);
        SN[t] = v / fmaxf(sqrtf(n2), 1e-12f);
    }
}

// ================= unified mma.sync fp16 GEMM ================================
enum { EPI_RAW0 = 0, EPI_RELU = 1, EPI_NB = 3, EPI_CELL0 = 4, EPI_CELL = 5 };

__device__ __forceinline__ void cp16(uint32_t daddr, const void* g) {
    asm volatile("cp.async.cg.shared.global [%0], [%1], 16;" :: "r"(daddr), "l"(g));
}

__device__ __forceinline__ void stage_load(char* sa, char* sb,
                                           const __half* __restrict__ Asrc,
                                           const __half* __restrict__ Bsrc,
                                           int lda, int ldb, int bm, int bn,
                                           int koff, int tid)
{
    #pragma unroll
    for (int i = 0; i < 2; i++) {
        int idx = i * 256 + tid;
        int row = idx >> 3, ch = idx & 7;
        uint32_t off = (uint32_t)(row * 128 + ch * 16);
        uint32_t sw  = off ^ ((off >> 3) & 0x70);
        cp16(smem_u32(sa + sw), Asrc + (size_t)(bm + row) * lda + koff + ch * 8);
    }
    #pragma unroll
    for (int i = 0; i < 4; i++) {
        int idx = i * 256 + tid;
        int row = idx >> 3, ch = idx & 7;
        uint32_t off = (uint32_t)(row * 128 + ch * 16);
        uint32_t sw  = off ^ ((off >> 3) & 0x70);
        cp16(smem_u32(sb + sw), Bsrc + (size_t)(bn + row) * ldb + koff + ch * 8);
    }
}

template <int EPI>
__device__ __forceinline__ void cell_store(int r, int u,
                                           float gi, float gf, float gg, float go,
                                           float* __restrict__ cvec,
                                           const float* __restrict__ qg,
                                           float* __restrict__ hout,
                                           __half* __restrict__ outh)
{
    size_t idx = (size_t)r * 256 + u;
    float cp = (EPI == EPI_CELL) ? cvec[idx] : 0.0f;
    float cn = sigf(gf) * cp + sigf(gi) * tanhf(gg);
    cvec[idx] = cn;
    float hv = qg[idx] + sigf(go) * tanhf(cn);
    hout[idx] = hv;
    outh[idx] = __float2half(hv);
}

template <int EPI>
__device__ __forceinline__ void epi_store(int gm, int gn, float v,
                                          float* __restrict__ C, int ldc,
                                          const float* __restrict__ bias,
                                          const float* __restrict__ extra,
                                          __half* __restrict__ outh)
{
    if (EPI == EPI_RAW0) {
        C[(size_t)gm * ldc + gn] = v;
    } else if (EPI == EPI_RELU) {
        float o = fmaxf(v + bias[gn], 0.0f);
        outh[(size_t)gm * ldc + gn] = __float2half(o);
    } else {  // EPI_NB
        float o = tanhf((v + 64.0f * bias[gn]) * extra[gm]);
        size_t idx = (size_t)(gm >> 1) * 256 + (size_t)(gm & 1) * 128 + gn;
        outh[idx] = __float2half(o);
    }
}

template <int EPI>
__global__ __launch_bounds__(256, 2)
void mma_gemm(const __half* __restrict__ A, int lda,
              const __half* __restrict__ B, int ldb,
              int K, size_t pstride,
              float* __restrict__ C, int ldc,
              const float* __restrict__ bias, const float* __restrict__ extra,
              __half* __restrict__ outh, __half* __restrict__ xwh,
              float* __restrict__ cvec, float* __restrict__ hout)
{
    constexpr int MI = 2;
    constexpr int ASZ = 64 * 128;          // 8 KB
    constexpr int STAGE = ASZ + 16384;     // 24 KB
    extern __shared__ char smem[];         // up to 4 stages = 96 KB
    const int tid  = threadIdx.x;
    const int wid  = tid >> 5;
    const int lane = tid & 31;
    const int bm = blockIdx.y * 64;
    const int bn = blockIdx.x * 128;
    const int zoff = blockIdx.z * K;
    if (EPI == EPI_RAW0) C += (size_t)blockIdx.z * pstride;
    const int warp_m = wid & 1;
    const int warp_n = wid >> 1;

    float acc[MI][4][4];
    #pragma unroll
    for (int mi = 0; mi < MI; mi++)
        #pragma unroll
        for (int nj = 0; nj < 4; nj++)
            #pragma unroll
            for (int q = 0; q < 4; q++) acc[mi][nj][q] = 0.0f;

    const int a_row_off = (lane & 7) + ((lane >> 3) & 1) * 8;
    const int a_ch_off  = lane >> 4;
    const int b_row_off = (lane >> 4) * 8 + (lane & 7);
    const int b_ch_off  = (lane >> 3) & 1;

    const int nt = K >> 6;   // <= 4

    for (int c = 0; c < nt; c++) {
        char* base = smem + c * STAGE;
        stage_load(base, base + ASZ, A, B, lda, ldb, bm, bn, zoff + c * 64, tid);
    }
    asm volatile("cp.async.commit_group;");
    asm volatile("cp.async.wait_group 0;");
    __syncthreads();

    for (int c = 0; c < nt; c++) {
        const uint32_t sa_base = smem_u32(smem + c * STAGE);
        const uint32_t sb_base = sa_base + ASZ;

        #pragma unroll
        for (int ks = 0; ks < 4; ks++) {
            uint32_t a[MI][4];
            #pragma unroll
            for (int mi = 0; mi < MI; mi++) {
                uint32_t row = warp_m * 32 + mi * 16 + a_row_off;
                uint32_t ch  = ks * 2 + a_ch_off;
                uint32_t off = row * 128 + ch * 16;
                uint32_t addr = sa_base + (off ^ ((off >> 3) & 0x70));
                asm volatile("ldmatrix.sync.aligned.m8n8.x4.shared.b16 {%0,%1,%2,%3}, [%4];"
                             : "=r"(a[mi][0]), "=r"(a[mi][1]), "=r"(a[mi][2]), "=r"(a[mi][3])
                             : "r"(addr));
            }
            uint32_t b[4][2];
            #pragma unroll
            for (int njp = 0; njp < 2; njp++) {
                uint32_t row = warp_n * 32 + njp * 16 + b_row_off;
                uint32_t ch  = ks * 2 + b_ch_off;
                uint32_t off = row * 128 + ch * 16;
                uint32_t addr = sb_base + (off ^ ((off >> 3) & 0x70));
                asm volatile("ldmatrix.sync.aligned.m8n8.x4.shared.b16 {%0,%1,%2,%3}, [%4];"
                             : "=r"(b[njp * 2][0]), "=r"(b[njp * 2][1]),
                               "=r"(b[njp * 2 + 1][0]), "=r"(b[njp * 2 + 1][1])
                             : "r"(addr));
            }
            #pragma unroll
            for (int mi = 0; mi < MI; mi++)
                #pragma unroll
                for (int nj = 0; nj < 4; nj++)
                    asm volatile(
                        "mma.sync.aligned.m16n8k16.row.col.f32.f16.f16.f32 "
                        "{%0,%1,%2,%3}, {%4,%5,%6,%7}, {%8,%9}, {%0,%1,%2,%3};"
                        : "+f"(acc[mi][nj][0]), "+f"(acc[mi][nj][1]),
                          "+f"(acc[mi][nj][2]), "+f"(acc[mi][nj][3])
                        : "r"(a[mi][0]), "r"(a[mi][1]), "r"(a[mi][2]), "r"(a[mi][3]),
                          "r"(b[nj][0]), "r"(b[nj][1]));
        }
    }

    if (EPI == EPI_CELL0 || EPI == EPI_CELL) {
        #pragma unroll
        for (int mi = 0; mi < MI; mi++) {
            int m0 = bm + warp_m * 32 + mi * 16 + (lane >> 2);
            #pragma unroll
            for (int nj = 0; nj < 4; nj++) {
                int n0 = bn + warp_n * 32 + nj * 8 + (lane & 3) * 2;
                float v0 = acc[mi][nj][0], v1 = acc[mi][nj][1];
                float v2 = acc[mi][nj][2], v3 = acc[mi][nj][3];
                if (EPI == EPI_CELL0) {
                    *(__half2*)(xwh + (size_t)m0 * 1024 + n0) =
                        __floats2half2_rn(v0, v1);
                    *(__half2*)(xwh + (size_t)(m0 + 8) * 1024 + n0) =
                        __floats2half2_rn(v2, v3);
                } else {
                    float2 x0 = __half22float2(*(const __half2*)(xwh + (size_t)m0 * 1024 + n0));
                    float2 x1 = __half22float2(*(const __half2*)(xwh + (size_t)(m0 + 8) * 1024 + n0));
                    v0 += x0.x; v1 += x0.y; v2 += x1.x; v3 += x1.y;
                }
                float bb0 = bias[n0], bb1 = bias[n0 + 1];
                v0 += bb0; v1 += bb1; v2 += bb0; v3 += bb1;
                float e0 = __shfl_xor_sync(0xFFFFFFFFu, v0, 1);
                float e1 = __shfl_xor_sync(0xFFFFFFFFu, v1, 1);
                float e2 = __shfl_xor_sync(0xFFFFFFFFu, v2, 1);
                float e3 = __shfl_xor_sync(0xFFFFFFFFu, v3, 1);
                if ((lane & 1) == 0) {
                    int u = n0 >> 2;
                    cell_store<EPI>(m0,     u, v0, v1, e0, e1, cvec, extra, hout, outh);
                    cell_store<EPI>(m0 + 8, u, v2, v3, e2, e3, cvec, extra, hout, outh);
                }
            }
        }
    } else {
        #pragma unroll
        for (int mi = 0; mi < MI; mi++) {
            int m0 = bm + warp_m * 32 + mi * 16 + (lane >> 2);
            #pragma unroll
            for (int nj = 0; nj < 4; nj++) {
                int n0 = bn + warp_n * 32 + nj * 8 + (lane & 3) * 2;
                epi_store<EPI>(m0,     n0,     acc[mi][nj][0], C, ldc, bias, extra, outh);
                epi_store<EPI>(m0,     n0 + 1, acc[mi][nj][1], C, ldc, bias, extra, outh);
                epi_store<EPI>(m0 + 8, n0,     acc[mi][nj][2], C, ldc, bias, extra, outh);
                epi_store<EPI>(m0 + 8, n0 + 1, acc[mi][nj][3], C, ldc, bias, extra, outh);
            }
        }
    }
}

// ================= layernorm over RES partials + fp16 out ====================
__global__ void ln_split_kernel(const float* __restrict__ ZP,
                                const __half* __restrict__ QNB,
                                const float* __restrict__ p2b,
                                const float* __restrict__ g,
                                const float* __restrict__ bb,
                                float* __restrict__ out,
                                __half* __restrict__ oh)
{
    __shared__ float sbuf[256];
    int r = blockIdx.x, t = threadIdx.x;
    size_t idx = (size_t)r * 256 + t;
    float z = ZP[idx] + ZP[PSTRIDE_RES + idx] + p2b[t] + __half2float(QNB[idx]);
    float mu = block_sum256(z, sbuf) * (1.0f / 256.0f);
    float d = z - mu;
    float var = block_sum256(d * d, sbuf) * (1.0f / 255.0f);
    float o = g[t] * d / (sqrtf(var) + 1e-6f) + bb[t];
    out[idx] = o;
    oh[idx] = __float2half(o);
}

// ================= final cosine similarity =================
__global__ void final_kernel(const float* __restrict__ h,
                             const float* __restrict__ sn,
                             float* __restrict__ out)
{
    __shared__ float sbuf[256];
    int b = blockIdx.x, t = threadIdx.x;
    float v = h[(size_t)b * 256 + t];
    float dot = block_sum256(v * sn[t], sbuf);
    float n2  = block_sum256(v * v, sbuf);
    if (t == 0) out[b] = dot / fmaxf(sqrtf(n2), 1e-12f);
}

// ================= launch =================
extern "C" void kernel_launch(void* const* d_in, const int* in_sizes, int n_in,
                              void* d_out, int out_size)
{
    (void)in_sizes; (void)n_in; (void)out_size;
    const int*   q_l_conn = (const int*)  d_in[2];
    const int*   q_l_deg  = (const int*)  d_in[3];
    const int*   q_r_conn = (const int*)  d_in[4];
    const int*   q_r_deg  = (const int*)  d_in[5];
    const int*   s_l_conn = (const int*)  d_in[6];
    const int*   s_l_deg  = (const int*)  d_in[7];
    const int*   s_r_conn = (const int*)  d_in[8];
    const int*   s_r_deg  = (const int*)  d_in[9];
    const float* emb      = (const float*)d_in[10];
    const float* gcn_w    = (const float*)d_in[11];
    const float* gcn_bias = (const float*)d_in[12];
    const float* proj1_w  = (const float*)d_in[13];
    const float* proj1_b  = (const float*)d_in[14];
    const float* proj2_w  = (const float*)d_in[15];
    const float* proj2_b  = (const float*)d_in[16];
    const float* ln_g     = (const float*)d_in[17];
    const float* ln_b     = (const float*)d_in[18];
    const float* w_ih     = (const float*)d_in[19];
    const float* w_hh     = (const float*)d_in[20];
    const float* b_ih     = (const float*)d_in[21];
    const float* b_hh     = (const float*)d_in[22];
    float* out = (float*)d_out;

    float* S = nullptr;
    cudaGetSymbolAddress((void**)&S, g_scratch);
    __half* HF = nullptr;
    cudaGetSymbolAddress((void**)&HF, g_hf);

    float* INVQ = S + O_INVQ;  float* ZP  = S + O_ZP;    float* QG = S + O_QG;
    float* SN   = S + O_SN;
    float* GB0  = S + O_GB0;   float* GB1 = S + O_GB1;
    float* C    = S + O_C;     float* H   = S + O_H;

    __half* BQ  = HF + H_BUFQ;  __half* QNB = HF + H_QNB;
    __half* HQ  = HF + H_HQ;    __half* QGH = HF + H_QG;
    __half* HH  = HF + H_HH;    __half* GW  = HF + H_GW;
    __half* P1  = HF + H_P1;    __half* P2  = HF + H_P2;
    __half* WIH = HF + H_WIH;   __half* WHH = HF + H_WHH;
    __half* XWH = HF + H_XW;

    const int SM4 = 4 * (64 * 128 + 16384);  // 98304
    cudaFuncSetAttribute(mma_gemm<EPI_RAW0>,  cudaFuncAttributeMaxDynamicSharedMemorySize, SM4);
    cudaFuncSetAttribute(mma_gemm<EPI_RELU>,  cudaFuncAttributeMaxDynamicSharedMemorySize, SM4);
    cudaFuncSetAttribute(mma_gemm<EPI_NB>,    cudaFuncAttributeMaxDynamicSharedMemorySize, SM4);
    cudaFuncSetAttribute(mma_gemm<EPI_CELL0>, cudaFuncAttributeMaxDynamicSharedMemorySize, SM4);
    cudaFuncSetAttribute(mma_gemm<EPI_CELL>,  cudaFuncAttributeMaxDynamicSharedMemorySize, SM4);

    // 1) ONE prep launch: weight fp16 + gb0 + all gathers (2 units/block)
    prep_all_kernel<<<3201 + 4101, 256>>>(
        gcn_w, proj1_w, proj2_w, w_ih, w_hh, b_ih, b_hh,
        q_l_conn, q_l_deg, q_r_conn, q_r_deg,
        s_l_conn, s_l_deg, s_r_conn, s_r_deg, emb,
        GW, P1, P2, WIH, WHH, GB0, BQ, INVQ);

    // 2) GCN (129 tiles of 64 rows): tanh+remap epilogue -> QNB fp16
    mma_gemm<EPI_NB><<<dim3(1, 129), 256, SM4>>>(
        BQ, 256, GW, 256, 256, 0, nullptr, 256,
        gcn_bias, INVQ, QNB, nullptr, nullptr, nullptr);

    // 3) proj1 (264 CTAs), proj2 split-K=2 (264 CTAs), LN folds partials+residual
    mma_gemm<EPI_RELU><<<dim3(4, 66), 256, SM4>>>(
        QNB, 256, P1, 256, 256, 0, nullptr, 512,
        proj1_b, nullptr, HQ, nullptr, nullptr, nullptr);
    mma_gemm<EPI_RAW0><<<dim3(2, 66, 2), 256, SM4>>>(
        HQ, 512, P2, 512, 256, PSTRIDE_RES, ZP, 256,
        nullptr, nullptr, nullptr, nullptr, nullptr, nullptr);
    ln_split_kernel<<<4101, 256>>>(ZP, QNB, proj2_b, ln_g, ln_b, QG, QGH);

    // 4) gb1 (+SN from block 0)
    gb1_sn_kernel<<<4, 256>>>(w_hh, QG, GB0, GB1, SN);

    // 5) LSTM: GEMM + fused cell epilogues (512 CTAs each); XW gates in fp16
    mma_gemm<EPI_CELL0><<<dim3(8, 64), 256, SM4>>>(
        QGH, 256, WIH, 256, 256, 0, nullptr, 1024,
        GB0, QG, HH, XWH, C, H);
    for (int t = 1; t < 4; t++) {
        mma_gemm<EPI_CELL><<<dim3(8, 64), 256, SM4>>>(
            HH, 256, WHH, 256, 256, 0, nullptr, 1024,
            GB1, QG, HH, XWH, C, H);
    }

    // 6) cosine similarity
    final_kernel<<<4096, 256>>>(H, SN, out);
}